// round 10
// baseline (speedup 1.0000x reference)
#include <cuda_runtime.h>
#include <cuda_fp16.h>
#include <math.h>
#include <stdint.h>

#define kN   32768
#define kE   (kN * 16)
#define kD   256
#define kH   8
#define kDH  32
#define kTD  256
#define kFFN 1024
#define kL   2
#define kQKV 768

// fp16 weight pool: [w_in | per-layer: wq wk wv wo w1 w2], all [K,N] row-major
#define WOFF_IN   0
#define WSEG_L    786432                       // per-layer halfs
#define WOFF_QKV(l) (65536 + (size_t)(l) * WSEG_L)
#define WOFF_WO(l)  (WOFF_QKV(l) + 196608)
#define WOFF_W1(l)  (WOFF_QKV(l) + 262144)
#define WOFF_W2(l)  (WOFF_QKV(l) + 524288)
#define WTOTAL (65536 + kL * WSEG_L)           // 1638400

// ---------------- device scratch ----------------
__device__ __half g_xh  [kN * kD];
__device__ __half g_xnh [kN * kD];
__device__ __half g_qh  [kN * kTD];
__device__ __half g_kh  [kN * kTD];
__device__ __half g_vh  [kN * kTD];
__device__ __half g_aggh[kN * kTD];
__device__ __half g_ffnh[kN * kFFN];
__device__ __half g_wh  [WTOTAL];
__device__ float  g_bqkv[kL * kQKV];
__device__ int    g_deg [kN];
__device__ int    g_fill[kN];
__device__ int    g_off [kN + 1];
__device__ int    g_csr [kE];

// ---------------- helpers ----------------
__device__ __forceinline__ uint32_t smem_u32(const void* p) {
    uint32_t a;
    asm("{ .reg .u64 t; cvta.to.shared.u64 t, %1; cvt.u32.u64 %0, t; }" : "=r"(a) : "l"(p));
    return a;
}
__device__ __forceinline__ void mma_f16(float& d0, float& d1, float& d2, float& d3,
                                        uint32_t a0, uint32_t a1, uint32_t a2, uint32_t a3,
                                        uint32_t b0, uint32_t b1) {
    asm volatile("mma.sync.aligned.m16n8k16.row.col.f32.f16.f16.f32 "
                 "{%0,%1,%2,%3}, {%4,%5,%6,%7}, {%8,%9}, {%0,%1,%2,%3};"
                 : "+f"(d0), "+f"(d1), "+f"(d2), "+f"(d3)
                 : "r"(a0), "r"(a1), "r"(a2), "r"(a3), "r"(b0), "r"(b1));
}
__device__ __forceinline__ void ldsm_x4(uint4& r, uint32_t addr) {
    asm volatile("ldmatrix.sync.aligned.m8n8.x4.shared.b16 {%0,%1,%2,%3}, [%4];"
                 : "=r"(r.x), "=r"(r.y), "=r"(r.z), "=r"(r.w) : "r"(addr));
}
__device__ __forceinline__ void ldsm_x4_t(uint4& r, uint32_t addr) {
    asm volatile("ldmatrix.sync.aligned.m8n8.x4.trans.shared.b16 {%0,%1,%2,%3}, [%4];"
                 : "=r"(r.x), "=r"(r.y), "=r"(r.z), "=r"(r.w) : "r"(addr));
}
__device__ __forceinline__ void cp16(uint32_t saddr, const void* gaddr) {
    asm volatile("cp.async.cg.shared.global [%0], [%1], 16;" :: "r"(saddr), "l"(gaddr));
}
__device__ __forceinline__ float gelu_exact(float x) {
    return 0.5f * x * (1.f + erff(x * 0.7071067811865475f));
}

// ---------------- fp16 GEMM: C = A[M,K] @ B[K,N] (B row-major, trans-ldsm) -
// flags: 0 plain fp32 out, 1 residual fp32 out, 2 gelu->fp16 aux,
//        3 qkv pack (q->C-as-half, k->aux, v->aux2); B col-block select /256
#define BM 128
#define BN 128
#define BK 32
#define ATILE_B (BM * BK * 2)            // 8192
#define STAGE_B (ATILE_B + BK * BN * 2)  // 16384
#define NSTAGE 4
#define DSMEM (NSTAGE * STAGE_B)         // 65536

__global__ void __launch_bounds__(256, 2)
gemm_tc(const __half* __restrict__ A, const __half* __restrict__ Bw, int ldb,
        const float* __restrict__ bias, float* __restrict__ C,
        __half* __restrict__ aux, __half* __restrict__ aux2,
        int M, int N, int K, int flags) {
    extern __shared__ char dsm[];
    uint32_t sbase = smem_u32(dsm);

    int tid = threadIdx.x;
    int lane = tid & 31;
    int wid = tid >> 5;
    int warp_row = wid >> 2;
    int warp_col = wid & 3;
    int row0 = blockIdx.y * BM, col0 = blockIdx.x * BN;

    const __half* Ag = A + (size_t)row0 * K;
    const __half* Bg;
    if (flags == 3) Bg = Bw + (size_t)(col0 >> 8) * 65536 + (col0 & 255);
    else            Bg = Bw + col0;

    // A copy: thread t handles chunks {2t, 2t+1}; rows m, 4 chunks/row
    int ca0 = tid * 2;
    int ar0 = ca0 >> 2,       ac0 = ca0 & 3;
    int ar1 = (ca0 + 1) >> 2, ac1 = (ca0 + 1) & 3;
    uint32_t sA0 = ar0 * 64 + (ac0 ^ ((ar0 >> 1) & 3)) * 16;
    uint32_t sA1 = ar1 * 64 + (ac1 ^ ((ar1 >> 1) & 3)) * 16;
    size_t gA0 = (size_t)ar0 * K + ac0 * 8;
    size_t gA1 = (size_t)ar1 * K + ac1 * 8;
    // B copy: thread t handles chunks {t, t+256}; rows k, 16 chunks/row
    int bk0 = tid >> 4,          bc0 = tid & 15;
    int bk1 = (tid + 256) >> 4,  bc1 = tid & 15;
    uint32_t sB0 = bk0 * 256 + ((bc0 ^ (bk0 & 7)) * 16);
    uint32_t sB1 = bk1 * 256 + ((bc1 ^ (bk1 & 7)) * 16);

    // A fragment read indices
    int lane_r = lane & 15;
    int lane_c = lane >> 4;
    int xorv = (lane_r >> 1) & 3;
    // B fragment (trans) indices
    int bl_k = (lane & 7) | (((lane >> 4) & 1) << 3);   // k within 16-block
    int bl_c8 = (lane >> 3) & 1;                        // n +8 selector

    float acc[4][4][4];
    #pragma unroll
    for (int i = 0; i < 4; ++i)
        #pragma unroll
        for (int j = 0; j < 4; ++j)
            #pragma unroll
            for (int q = 0; q < 4; ++q) acc[i][j][q] = 0.f;

    int nIter = K / BK;

    #pragma unroll
    for (int s = 0; s < 3; ++s) {
        uint32_t Ab = sbase + s * STAGE_B;
        uint32_t Bb = Ab + ATILE_B;
        int kk = s * BK;
        cp16(Ab + sA0, Ag + gA0 + kk);
        cp16(Ab + sA1, Ag + gA1 + kk);
        cp16(Bb + sB0, Bg + (size_t)(kk + bk0) * ldb + bc0 * 8);
        cp16(Bb + sB1, Bg + (size_t)(kk + bk1) * ldb + bc1 * 8);
        asm volatile("cp.async.commit_group;");
    }

    for (int it = 0; it < nIter; ++it) {
        asm volatile("cp.async.wait_group 2;");
        __syncthreads();
        uint32_t Ab = sbase + (it & 3) * STAGE_B;
        uint32_t Bb = Ab + ATILE_B;

        #pragma unroll
        for (int kc = 0; kc < 2; ++kc) {
            uint32_t csA = (uint32_t)(((kc * 2 + lane_c) ^ xorv) * 16);
            int k_loc = kc * 16 + bl_k;
            uint4 af[4], bm[2];
            #pragma unroll
            for (int mt = 0; mt < 4; ++mt)
                ldsm_x4(af[mt], Ab + (uint32_t)(warp_row * 64 + mt * 16 + lane_r) * 64 + csA);
            #pragma unroll
            for (int ntp = 0; ntp < 2; ++ntp) {
                int cB = (warp_col * 4 + ntp * 2 + bl_c8) ^ (k_loc & 7);
                ldsm_x4_t(bm[ntp], Bb + (uint32_t)k_loc * 256 + (uint32_t)cB * 16);
            }
            #pragma unroll
            for (int mt = 0; mt < 4; ++mt) {
                mma_f16(acc[mt][0][0], acc[mt][0][1], acc[mt][0][2], acc[mt][0][3],
                        af[mt].x, af[mt].y, af[mt].z, af[mt].w, bm[0].x, bm[0].z);
                mma_f16(acc[mt][1][0], acc[mt][1][1], acc[mt][1][2], acc[mt][1][3],
                        af[mt].x, af[mt].y, af[mt].z, af[mt].w, bm[0].y, bm[0].w);
                mma_f16(acc[mt][2][0], acc[mt][2][1], acc[mt][2][2], acc[mt][2][3],
                        af[mt].x, af[mt].y, af[mt].z, af[mt].w, bm[1].x, bm[1].z);
                mma_f16(acc[mt][3][0], acc[mt][3][1], acc[mt][3][2], acc[mt][3][3],
                        af[mt].x, af[mt].y, af[mt].z, af[mt].w, bm[1].y, bm[1].w);
            }
        }
        if (it + 3 < nIter) {
            uint32_t Aw = sbase + ((it + 3) & 3) * STAGE_B;
            uint32_t Bwr = Aw + ATILE_B;
            int kk = (it + 3) * BK;
            cp16(Aw + sA0, Ag + gA0 + kk);
            cp16(Aw + sA1, Ag + gA1 + kk);
            cp16(Bwr + sB0, Bg + (size_t)(kk + bk0) * ldb + bc0 * 8);
            cp16(Bwr + sB1, Bg + (size_t)(kk + bk1) * ldb + bc1 * 8);
        }
        asm volatile("cp.async.commit_group;");
    }

    // ---- epilogue ----
    int g = lane >> 2, tg = lane & 3;
    #pragma unroll
    for (int mt = 0; mt < 4; ++mt) {
        int rbase = row0 + warp_row * 64 + mt * 16 + g;
        #pragma unroll
        for (int nt = 0; nt < 4; ++nt) {
            int c = col0 + warp_col * 32 + nt * 8 + tg * 2;
            float2 bs = *reinterpret_cast<const float2*>(&bias[c]);
            float v0 = acc[mt][nt][0] + bs.x;
            float v1 = acc[mt][nt][1] + bs.y;
            float v2 = acc[mt][nt][2] + bs.x;
            float v3 = acc[mt][nt][3] + bs.y;
            if (flags == 2) {
                v0 = gelu_exact(v0); v1 = gelu_exact(v1);
                v2 = gelu_exact(v2); v3 = gelu_exact(v3);
                *reinterpret_cast<__half2*>(aux + (size_t)rbase * N + c)       = __floats2half2_rn(v0, v1);
                *reinterpret_cast<__half2*>(aux + (size_t)(rbase + 8) * N + c) = __floats2half2_rn(v2, v3);
            } else if (flags == 3) {
                __half* dst = (col0 < 256) ? reinterpret_cast<__half*>(C)
                             : (col0 >= 512) ? aux2 : aux;
                int cm = c & 255;
                *reinterpret_cast<__half2*>(dst + (size_t)rbase * kTD + cm)       = __floats2half2_rn(v0, v1);
                *reinterpret_cast<__half2*>(dst + (size_t)(rbase + 8) * kTD + cm) = __floats2half2_rn(v2, v3);
            } else {
                float2* cp0 = reinterpret_cast<float2*>(C + (size_t)rbase * N + c);
                float2* cp1 = reinterpret_cast<float2*>(C + (size_t)(rbase + 8) * N + c);
                if (flags == 1) {
                    float2 o0 = *cp0, o1 = *cp1;
                    v0 += o0.x; v1 += o0.y; v2 += o1.x; v3 += o1.y;
                }
                float2 r0 = {v0, v1}, r1 = {v2, v3};
                *cp0 = r0;
                *cp1 = r1;
            }
        }
    }
}

// ---------------- fused weight convert fp32->fp16 (all 13 matrices) -------
__global__ void cvt_w(const float* __restrict__ w_in,
                      const float* __restrict__ wq, const float* __restrict__ wk,
                      const float* __restrict__ wv, const float* __restrict__ wo,
                      const float* __restrict__ w1, const float* __restrict__ w2) {
    size_t i = ((size_t)blockIdx.x * 256 + threadIdx.x) * 8;   // WTOTAL/8 threads
    int seg = (int)(i >> 16);
    size_t off = i & 65535;
    const float* src;
    if (seg == 0) src = w_in + off;
    else {
        int t = seg - 1, l = t / 12, s = t % 12;
        if (s < 3)      src = ((s == 0) ? wq : (s == 1) ? wk : wv) + (size_t)l * 65536 + off;
        else if (s == 3) src = wo + (size_t)l * 65536 + off;
        else if (s < 8)  src = w1 + (size_t)l * 262144 + (size_t)(s - 4) * 65536 + off;
        else             src = w2 + (size_t)l * 262144 + (size_t)(s - 8) * 65536 + off;
    }
    float4 v0 = reinterpret_cast<const float4*>(src)[0];
    float4 v1 = reinterpret_cast<const float4*>(src)[1];
    __half2 h0 = __floats2half2_rn(v0.x, v0.y);
    __half2 h1 = __floats2half2_rn(v0.z, v0.w);
    __half2 h2 = __floats2half2_rn(v1.x, v1.y);
    __half2 h3 = __floats2half2_rn(v1.z, v1.w);
    uint4 u = {*reinterpret_cast<uint32_t*>(&h0), *reinterpret_cast<uint32_t*>(&h1),
               *reinterpret_cast<uint32_t*>(&h2), *reinterpret_cast<uint32_t*>(&h3)};
    *reinterpret_cast<uint4*>(g_wh + i) = u;
}

__global__ void cvt_x(const float* __restrict__ x, __half* __restrict__ xh) {
    int i = blockIdx.x * 256 + threadIdx.x;
    float4 v = reinterpret_cast<const float4*>(x)[i];
    __half2 h0 = __floats2half2_rn(v.x, v.y);
    __half2 h1 = __floats2half2_rn(v.z, v.w);
    uint2 u = {*reinterpret_cast<uint32_t*>(&h0), *reinterpret_cast<uint32_t*>(&h1)};
    reinterpret_cast<uint2*>(xh)[i] = u;
}

__global__ void pack_bias(const float* bq, const float* bk, const float* bv) {
    int t = blockIdx.x * 256 + threadIdx.x;
    int l = t / kQKV, r = t % kQKV;
    const float* s = (r < 256) ? bq + l * kTD + r
                   : (r < 512) ? bk + l * kTD + (r - 256)
                               : bv + l * kTD + (r - 512);
    g_bqkv[t] = *s;
}

// ---------------- CSR build ----------------
__global__ void deg_count_kernel(const int* __restrict__ ei) {
    int e = blockIdx.x * 256 + threadIdx.x;
    if (e < kE) atomicAdd(&g_deg[ei[kE + e]], 1);
}
__global__ void prefix_kernel() {
    __shared__ int sums[1024];
    int t = threadIdx.x;
    int base = t * 32;
    int s = 0;
    #pragma unroll 4
    for (int i = 0; i < 32; ++i) s += g_deg[base + i];
    sums[t] = s;
    __syncthreads();
    for (int o = 1; o < 1024; o <<= 1) {
        int v = (t >= o) ? sums[t - o] : 0;
        __syncthreads();
        sums[t] += v;
        __syncthreads();
    }
    int run = sums[t] - s;
    for (int i = 0; i < 32; ++i) { g_off[base + i] = run; run += g_deg[base + i]; }
    if (t == 1023) g_off[kN] = run;
}
__global__ void scatter_kernel(const int* __restrict__ ei) {
    int e = blockIdx.x * 256 + threadIdx.x;
    if (e < kE) {
        int d = ei[kE + e];
        int pos = g_off[d] + atomicAdd(&g_fill[d], 1);
        g_csr[pos] = ei[e];
    }
}

// ---------------- LayerNorm: warp per row, fp32 in, fp16 out --------------
__global__ void __launch_bounds__(256)
ln_kernel(const float* __restrict__ x, const float* __restrict__ gg,
          const float* __restrict__ bb, __half* __restrict__ y) {
    int lane = threadIdx.x & 31;
    int row = blockIdx.x * 8 + (threadIdx.x >> 5);
    const float4* xr = reinterpret_cast<const float4*>(x + (size_t)row * kD);
    float4 a0 = xr[lane];
    float4 a1 = xr[lane + 32];
    float s = a0.x + a0.y + a0.z + a0.w + a1.x + a1.y + a1.z + a1.w;
    float q = a0.x*a0.x + a0.y*a0.y + a0.z*a0.z + a0.w*a0.w
            + a1.x*a1.x + a1.y*a1.y + a1.z*a1.z + a1.w*a1.w;
    #pragma unroll
    for (int o = 16; o; o >>= 1) {
        s += __shfl_xor_sync(~0u, s, o);
        q += __shfl_xor_sync(~0u, q, o);
    }
    float mean = s * (1.f / kD);
    float var = q * (1.f / kD) - mean * mean;
    float inv = rsqrtf(var + 1e-5f);
    float4 g0 = reinterpret_cast<const float4*>(gg)[lane];
    float4 g1 = reinterpret_cast<const float4*>(gg)[lane + 32];
    float4 b0 = reinterpret_cast<const float4*>(bb)[lane];
    float4 b1 = reinterpret_cast<const float4*>(bb)[lane + 32];
    __half2 o0 = __floats2half2_rn((a0.x - mean) * inv * g0.x + b0.x, (a0.y - mean) * inv * g0.y + b0.y);
    __half2 o1 = __floats2half2_rn((a0.z - mean) * inv * g0.z + b0.z, (a0.w - mean) * inv * g0.w + b0.w);
    __half2 o2 = __floats2half2_rn((a1.x - mean) * inv * g1.x + b1.x, (a1.y - mean) * inv * g1.y + b1.y);
    __half2 o3 = __floats2half2_rn((a1.z - mean) * inv * g1.z + b1.z, (a1.w - mean) * inv * g1.w + b1.w);
    uint2 u0 = {*reinterpret_cast<uint32_t*>(&o0), *reinterpret_cast<uint32_t*>(&o1)};
    uint2 u1 = {*reinterpret_cast<uint32_t*>(&o2), *reinterpret_cast<uint32_t*>(&o3)};
    *reinterpret_cast<uint2*>(y + (size_t)row * kD + lane * 4)       = u0;
    *reinterpret_cast<uint2*>(y + (size_t)row * kD + 128 + lane * 4) = u1;
}

// ---------------- Edge attention: warp = 2 heads, lane = 2 dims -----------
__global__ void __launch_bounds__(128)
attn_kernel() {
    int tid = threadIdx.x;
    int lane = tid & 31;
    int w = tid >> 5;
    int node = blockIdx.x;
    int head = w * 2 + (lane >> 4);
    int j = lane & 15;
    int hd0 = head * kDH + 2 * j;

    int beg = g_off[node], end = g_off[node + 1];
    __half2* aggp = reinterpret_cast<__half2*>(g_aggh);
    int outi = (node * kTD + hd0) >> 1;
    if (beg == end) { aggp[outi] = __floats2half2_rn(0.f, 0.f); return; }

    const __half2* qp = reinterpret_cast<const __half2*>(g_qh);
    float2 qf = __half22float2(qp[(size_t)(node * kTD + hd0) >> 1]);
    float qv0 = qf.x * 0.17677669529663687f;
    float qv1 = qf.y * 0.17677669529663687f;
    const __half2* kp = reinterpret_cast<const __half2*>(g_kh);
    const __half2* vp = reinterpret_cast<const __half2*>(g_vh);

    float l = 0.f, acc0 = 0.f, acc1 = 0.f;
    {
        float2 kk = __half22float2(kp[(size_t)(node * kTD + hd0) >> 1]);
        float2 vv = __half22float2(vp[(size_t)(node * kTD + hd0) >> 1]);
        float s = qv0 * kk.x + qv1 * kk.y;
        s += __shfl_xor_sync(~0u, s, 8);
        s += __shfl_xor_sync(~0u, s, 4);
        s += __shfl_xor_sync(~0u, s, 2);
        s += __shfl_xor_sync(~0u, s, 1);
        float p = __expf(s);
        l += p; acc0 += p * vv.x; acc1 += p * vv.y;
    }
    int i = beg;
    for (; i + 1 < end; i += 2) {
        int s0 = g_csr[i], s1 = g_csr[i + 1];
        size_t i0 = ((size_t)s0 * kTD + hd0) >> 1;
        size_t i1 = ((size_t)s1 * kTD + hd0) >> 1;
        float2 k0 = __half22float2(kp[i0]);
        float2 k1 = __half22float2(kp[i1]);
        float2 v0 = __half22float2(vp[i0]);
        float2 v1 = __half22float2(vp[i1]);
        float a = qv0 * k0.x + qv1 * k0.y;
        float b = qv0 * k1.x + qv1 * k1.y;
        a += __shfl_xor_sync(~0u, a, 8); b += __shfl_xor_sync(~0u, b, 8);
        a += __shfl_xor_sync(~0u, a, 4); b += __shfl_xor_sync(~0u, b, 4);
        a += __shfl_xor_sync(~0u, a, 2); b += __shfl_xor_sync(~0u, b, 2);
        a += __shfl_xor_sync(~0u, a, 1); b += __shfl_xor_sync(~0u, b, 1);
        float p0 = __expf(a), p1 = __expf(b);
        l += p0 + p1;
        acc0 += p0 * v0.x + p1 * v1.x;
        acc1 += p0 * v0.y + p1 * v1.y;
    }
    if (i < end) {
        int s0 = g_csr[i];
        size_t i0 = ((size_t)s0 * kTD + hd0) >> 1;
        float2 kk = __half22float2(kp[i0]);
        float2 vv = __half22float2(vp[i0]);
        float s = qv0 * kk.x + qv1 * kk.y;
        s += __shfl_xor_sync(~0u, s, 8);
        s += __shfl_xor_sync(~0u, s, 4);
        s += __shfl_xor_sync(~0u, s, 2);
        s += __shfl_xor_sync(~0u, s, 1);
        float p = __expf(s);
        l += p; acc0 += p * vv.x; acc1 += p * vv.y;
    }
    float inv = 1.f / l;
    aggp[outi] = __floats2half2_rn(acc0 * inv, acc1 * inv);
}

// ---------------- host ----------------
static inline void gemm(const __half* A, const __half* Bw, int ldb, const float* bias,
                        float* C, __half* aux, __half* aux2,
                        int M, int N, int K, int flags) {
    dim3 g(N / BN, M / BM);
    gemm_tc<<<g, 256, DSMEM>>>(A, Bw, ldb, bias, C, aux, aux2, M, N, K, flags);
}

extern "C" void kernel_launch(void* const* d_in, const int* in_sizes, int n_in,
                              void* d_out, int out_size) {
    const float* x     = (const float*)d_in[0];
    const int*   ei    = (const int*)  d_in[1];
    const float* w_in  = (const float*)d_in[2];
    const float* b_in  = (const float*)d_in[3];
    const float* ln1_g = (const float*)d_in[4];
    const float* ln1_b = (const float*)d_in[5];
    const float* ln2_g = (const float*)d_in[6];
    const float* ln2_b = (const float*)d_in[7];
    const float* wq = (const float*)d_in[8];  const float* bq = (const float*)d_in[9];
    const float* wk = (const float*)d_in[10]; const float* bk = (const float*)d_in[11];
    const float* wv = (const float*)d_in[12]; const float* bv = (const float*)d_in[13];
    const float* wo = (const float*)d_in[14]; const float* bo = (const float*)d_in[15];
    const float* w1 = (const float*)d_in[16]; const float* b1 = (const float*)d_in[17];
    const float* w2 = (const float*)d_in[18]; const float* b2 = (const float*)d_in[19];
    float* h = (float*)d_out;

    cudaFuncSetAttribute(gemm_tc, cudaFuncAttributeMaxDynamicSharedMemorySize, DSMEM);

    __half *xh, *xnh, *qh, *kh, *vh, *aggh, *ffnh, *wh;
    float *bqkv;
    int *deg, *fill;
    cudaGetSymbolAddress((void**)&xh,    g_xh);
    cudaGetSymbolAddress((void**)&xnh,   g_xnh);
    cudaGetSymbolAddress((void**)&qh,    g_qh);
    cudaGetSymbolAddress((void**)&kh,    g_kh);
    cudaGetSymbolAddress((void**)&vh,    g_vh);
    cudaGetSymbolAddress((void**)&aggh,  g_aggh);
    cudaGetSymbolAddress((void**)&ffnh,  g_ffnh);
    cudaGetSymbolAddress((void**)&wh,    g_wh);
    cudaGetSymbolAddress((void**)&bqkv,  g_bqkv);
    cudaGetSymbolAddress((void**)&deg,   g_deg);
    cudaGetSymbolAddress((void**)&fill,  g_fill);

    // ---- CSR by dst ----
    cudaMemsetAsync(deg,  0, kN * sizeof(int));
    cudaMemsetAsync(fill, 0, kN * sizeof(int));
    deg_count_kernel<<<kE / 256, 256>>>(ei);
    prefix_kernel<<<1, 1024>>>();
    scatter_kernel<<<kE / 256, 256>>>(ei);

    // ---- prep: conversions (no transposes needed any more) ----
    cvt_x<<<kN * kD / 4 / 256, 256>>>(x, xh);
    cvt_w<<<WTOTAL / 8 / 256, 256>>>(w_in, wq, wk, wv, wo, w1, w2);
    pack_bias<<<kL * kQKV / 256, 256>>>(bq, bk, bv);

    // ---- input projection ----
    gemm(xh, wh + WOFF_IN, kD, b_in, h, nullptr, nullptr, kN, kD, kD, 0);

    for (int l = 0; l < kL; ++l) {
        ln_kernel<<<kN / 8, 256>>>(h, ln1_g + l * kD, ln1_b + l * kD, xnh);
        gemm(xnh, wh + WOFF_QKV(l), kTD, bqkv + (size_t)l * kQKV,
             (float*)qh, kh, vh, kN, kQKV, kD, 3);
        attn_kernel<<<kN, 128>>>();
        gemm(aggh, wh + WOFF_WO(l), kD, bo + (size_t)l * kD,
             h, nullptr, nullptr, kN, kD, kTD, 1);
        ln_kernel<<<kN / 8, 256>>>(h, ln2_g + l * kD, ln2_b + l * kD, xnh);
        gemm(xnh, wh + WOFF_W1(l), kFFN, b1 + (size_t)l * kFFN,
             nullptr, ffnh, nullptr, kN, kFFN, kD, 2);
        gemm(ffnh, wh + WOFF_W2(l), kD, b2 + (size_t)l * kD,
             h, nullptr, nullptr, kN, kD, kFFN, 1);
    }
}

// round 11
// speedup vs baseline: 1.4791x; 1.4791x over previous
#include <cuda_runtime.h>
#include <cuda_fp16.h>
#include <math.h>
#include <stdint.h>

#define kN   32768
#define kE   (kN * 16)
#define kD   256
#define kH   8
#define kDH  32
#define kTD  256
#define kFFN 1024
#define kL   2
#define kQKV 768

// ---------------- device scratch ----------------
__device__ __half g_xh  [kN * kD];
__device__ __half g_xnh [kN * kD];
__device__ __half g_qh  [kN * kTD];
__device__ __half g_kh  [kN * kTD];
__device__ __half g_vh  [kN * kTD];
__device__ __half g_aggh[kN * kTD];
__device__ __half g_ffnh[kN * kFFN];
__device__ __half g_winT [kD * kD];
__device__ __half g_wqkvT[kL * kQKV * kD];
__device__ __half g_woT  [kL * kD * kTD];
__device__ __half g_w1T  [kL * kFFN * kD];
__device__ __half g_w2T  [kL * kD * kFFN];
__device__ float  g_bqkv [kL * kQKV];
__device__ int    g_deg [kN];
__device__ int    g_fill[kN];
__device__ int    g_off [kN + 1];
__device__ int    g_csr [kE];

// ---------------- helpers ----------------
__device__ __forceinline__ uint32_t smem_u32(const void* p) {
    uint32_t a;
    asm("{ .reg .u64 t; cvta.to.shared.u64 t, %1; cvt.u32.u64 %0, t; }" : "=r"(a) : "l"(p));
    return a;
}
__device__ __forceinline__ void mma_f16(float& d0, float& d1, float& d2, float& d3,
                                        uint32_t a0, uint32_t a1, uint32_t a2, uint32_t a3,
                                        uint32_t b0, uint32_t b1) {
    asm volatile("mma.sync.aligned.m16n8k16.row.col.f32.f16.f16.f32 "
                 "{%0,%1,%2,%3}, {%4,%5,%6,%7}, {%8,%9}, {%0,%1,%2,%3};"
                 : "+f"(d0), "+f"(d1), "+f"(d2), "+f"(d3)
                 : "r"(a0), "r"(a1), "r"(a2), "r"(a3), "r"(b0), "r"(b1));
}
__device__ __forceinline__ void ldsm_x4(uint4& r, uint32_t addr) {
    asm volatile("ldmatrix.sync.aligned.m8n8.x4.shared.b16 {%0,%1,%2,%3}, [%4];"
                 : "=r"(r.x), "=r"(r.y), "=r"(r.z), "=r"(r.w) : "r"(addr));
}
__device__ __forceinline__ void cp16(uint32_t saddr, const void* gaddr) {
    asm volatile("cp.async.cg.shared.global [%0], [%1], 16;" :: "r"(saddr), "l"(gaddr));
}
__device__ __forceinline__ float gelu_exact(float x) {
    return 0.5f * x * (1.f + erff(x * 0.7071067811865475f));
}

// ---------------- fp16 cp.async+ldmatrix GEMM: C = A[M,K] @ Bt[N,K]^T -----
// flags: 0 plain fp32 out, 1 residual fp32 out, 2 gelu->fp16 aux,
//        3 qkv pack (q fp16 -> C-as-half, k in aux, v in aux2)
#define BM 128
#define BN 128
#define BK 32
#define ATILE_B (BM * BK * 2)            // 8192
#define STAGE_B (ATILE_B + BN * BK * 2)  // 16384
#define NSTAGE 4
#define DSMEM (NSTAGE * STAGE_B)         // 65536

__global__ void __launch_bounds__(256, 2)
gemm_tc(const __half* __restrict__ A, const __half* __restrict__ Bt,
        const float* __restrict__ bias, float* __restrict__ C,
        __half* __restrict__ aux, __half* __restrict__ aux2,
        int M, int N, int K, int flags) {
    extern __shared__ char dsm[];
    uint32_t sbase = smem_u32(dsm);

    int tid = threadIdx.x;
    int lane = tid & 31;
    int wid = tid >> 5;
    int warp_row = wid >> 2;
    int warp_col = wid & 3;
    int row0 = blockIdx.y * BM, col0 = blockIdx.x * BN;

    const __half* Ag = A + (size_t)row0 * K;
    const __half* Bg = Bt + (size_t)col0 * K;

    // copy indices: thread t copies chunks 2t, 2t+1 of A and of B
    int id0 = tid * 2;
    int crow0 = id0 >> 2,       cc0 = id0 & 3;
    int crow1 = (id0 + 1) >> 2, cc1 = (id0 + 1) & 3;
    int cs0 = cc0 ^ ((crow0 >> 1) & 3);
    int cs1 = cc1 ^ ((crow1 >> 1) & 3);
    uint32_t sA0 = crow0 * 64 + cs0 * 16;
    uint32_t sA1 = crow1 * 64 + cs1 * 16;
    size_t gA0 = (size_t)crow0 * K + cc0 * 8;
    size_t gA1 = (size_t)crow1 * K + cc1 * 8;

    // fragment read indices
    int lane_r = lane & 15;
    int lane_c = lane >> 4;
    int xorv = (lane_r >> 1) & 3;

    float acc[4][4][4];
    #pragma unroll
    for (int i = 0; i < 4; ++i)
        #pragma unroll
        for (int j = 0; j < 4; ++j)
            #pragma unroll
            for (int q = 0; q < 4; ++q) acc[i][j][q] = 0.f;

    int nIter = K / BK;

    // prologue: issue 3 stages
    #pragma unroll
    for (int s = 0; s < 3; ++s) {
        uint32_t Ab = sbase + s * STAGE_B;
        uint32_t Bb = Ab + ATILE_B;
        int kk = s * BK;
        cp16(Ab + sA0, Ag + gA0 + kk);
        cp16(Ab + sA1, Ag + gA1 + kk);
        cp16(Bb + sA0, Bg + gA0 + kk);
        cp16(Bb + sA1, Bg + gA1 + kk);
        asm volatile("cp.async.commit_group;");
    }

    for (int it = 0; it < nIter; ++it) {
        asm volatile("cp.async.wait_group 2;");
        __syncthreads();
        uint32_t Ab = sbase + (it & 3) * STAGE_B;
        uint32_t Bb = Ab + ATILE_B;

        #pragma unroll
        for (int kc = 0; kc < 2; ++kc) {
            uint32_t cs = (uint32_t)(((kc * 2 + lane_c) ^ xorv) * 16);
            uint4 af[4], bm[2];
            #pragma unroll
            for (int mt = 0; mt < 4; ++mt)
                ldsm_x4(af[mt], Ab + (uint32_t)(warp_row * 64 + mt * 16 + lane_r) * 64 + cs);
            #pragma unroll
            for (int ntp = 0; ntp < 2; ++ntp)
                ldsm_x4(bm[ntp], Bb + (uint32_t)(warp_col * 32 + ntp * 16 + lane_r) * 64 + cs);
            #pragma unroll
            for (int mt = 0; mt < 4; ++mt) {
                mma_f16(acc[mt][0][0], acc[mt][0][1], acc[mt][0][2], acc[mt][0][3],
                        af[mt].x, af[mt].y, af[mt].z, af[mt].w, bm[0].x, bm[0].z);
                mma_f16(acc[mt][1][0], acc[mt][1][1], acc[mt][1][2], acc[mt][1][3],
                        af[mt].x, af[mt].y, af[mt].z, af[mt].w, bm[0].y, bm[0].w);
                mma_f16(acc[mt][2][0], acc[mt][2][1], acc[mt][2][2], acc[mt][2][3],
                        af[mt].x, af[mt].y, af[mt].z, af[mt].w, bm[1].x, bm[1].z);
                mma_f16(acc[mt][3][0], acc[mt][3][1], acc[mt][3][2], acc[mt][3][3],
                        af[mt].x, af[mt].y, af[mt].z, af[mt].w, bm[1].y, bm[1].w);
            }
        }
        if (it + 3 < nIter) {
            uint32_t Aw = sbase + ((it + 3) & 3) * STAGE_B;
            uint32_t Bw = Aw + ATILE_B;
            int kk = (it + 3) * BK;
            cp16(Aw + sA0, Ag + gA0 + kk);
            cp16(Aw + sA1, Ag + gA1 + kk);
            cp16(Bw + sA0, Bg + gA0 + kk);
            cp16(Bw + sA1, Bg + gA1 + kk);
        }
        asm volatile("cp.async.commit_group;");
    }

    // ---- epilogue ----
    int g = lane >> 2, tg = lane & 3;
    bool isq = (col0 < 256);
    bool isv = (col0 >= 512);
    #pragma unroll
    for (int mt = 0; mt < 4; ++mt) {
        int rbase = row0 + warp_row * 64 + mt * 16 + g;
        #pragma unroll
        for (int nt = 0; nt < 4; ++nt) {
            int c = col0 + warp_col * 32 + nt * 8 + tg * 2;
            float2 bs = *reinterpret_cast<const float2*>(&bias[c]);
            float v0 = acc[mt][nt][0] + bs.x;
            float v1 = acc[mt][nt][1] + bs.y;
            float v2 = acc[mt][nt][2] + bs.x;
            float v3 = acc[mt][nt][3] + bs.y;
            if (flags == 2) {
                v0 = gelu_exact(v0); v1 = gelu_exact(v1);
                v2 = gelu_exact(v2); v3 = gelu_exact(v3);
                *reinterpret_cast<__half2*>(aux + (size_t)rbase * N + c)       = __floats2half2_rn(v0, v1);
                *reinterpret_cast<__half2*>(aux + (size_t)(rbase + 8) * N + c) = __floats2half2_rn(v2, v3);
            } else if (flags == 3) {
                __half* dst = isq ? reinterpret_cast<__half*>(C) : (isv ? aux2 : aux);
                int cm = c & 255;
                *reinterpret_cast<__half2*>(dst + (size_t)rbase * kTD + cm)       = __floats2half2_rn(v0, v1);
                *reinterpret_cast<__half2*>(dst + (size_t)(rbase + 8) * kTD + cm) = __floats2half2_rn(v2, v3);
            } else {
                float2* cp0 = reinterpret_cast<float2*>(C + (size_t)rbase * N + c);
                float2* cp1 = reinterpret_cast<float2*>(C + (size_t)(rbase + 8) * N + c);
                if (flags == 1) {
                    float2 o0 = *cp0, o1 = *cp1;
                    v0 += o0.x; v1 += o0.y; v2 += o1.x; v3 += o1.y;
                }
                float2 r0 = {v0, v1}, r1 = {v2, v3};
                *cp0 = r0;
                *cp1 = r1;
            }
        }
    }
}

// ---------------- transpose + fp32->fp16 ----------------
__global__ void transpose_h(const float* __restrict__ src, __half* __restrict__ dst,
                            int R, int C) {
    __shared__ float t[32][33];
    int bx = blockIdx.x * 32, by = blockIdx.y * 32;
    int x = bx + threadIdx.x;
    #pragma unroll
    for (int j = 0; j < 32; j += 8)
        t[threadIdx.y + j][threadIdx.x] = src[(size_t)(by + threadIdx.y + j) * C + x];
    __syncthreads();
    int xo = by + threadIdx.x;
    #pragma unroll
    for (int j = 0; j < 32; j += 8)
        dst[(size_t)(bx + threadIdx.y + j) * R + xo] = __float2half_rn(t[threadIdx.x][threadIdx.y + j]);
}
__global__ void transpose3_h(const float* s0, const float* s1, const float* s2,
                             __half* __restrict__ dst, int R, int C) {
    __shared__ float t[32][33];
    const float* src = (blockIdx.z == 0) ? s0 : (blockIdx.z == 1) ? s1 : s2;
    __half* d = dst + (size_t)blockIdx.z * C * R;
    int bx = blockIdx.x * 32, by = blockIdx.y * 32;
    int x = bx + threadIdx.x;
    #pragma unroll
    for (int j = 0; j < 32; j += 8)
        t[threadIdx.y + j][threadIdx.x] = src[(size_t)(by + threadIdx.y + j) * C + x];
    __syncthreads();
    int xo = by + threadIdx.x;
    #pragma unroll
    for (int j = 0; j < 32; j += 8)
        d[(size_t)(bx + threadIdx.y + j) * R + xo] = __float2half_rn(t[threadIdx.x][threadIdx.y + j]);
}

__global__ void cvt_x(const float* __restrict__ x, __half* __restrict__ xh) {
    int i = blockIdx.x * 256 + threadIdx.x;
    float4 v = reinterpret_cast<const float4*>(x)[i];
    __half2 h0 = __floats2half2_rn(v.x, v.y);
    __half2 h1 = __floats2half2_rn(v.z, v.w);
    uint2 u = {*reinterpret_cast<uint32_t*>(&h0), *reinterpret_cast<uint32_t*>(&h1)};
    reinterpret_cast<uint2*>(xh)[i] = u;
}

__global__ void pack_bias(const float* bq, const float* bk, const float* bv) {
    int t = blockIdx.x * 256 + threadIdx.x;
    int l = t / kQKV, r = t % kQKV;
    const float* s = (r < 256) ? bq + l * kTD + r
                   : (r < 512) ? bk + l * kTD + (r - 256)
                               : bv + l * kTD + (r - 512);
    g_bqkv[t] = *s;
}

// ---------------- CSR build ----------------
__global__ void deg_count_kernel(const int* __restrict__ ei) {
    int e = blockIdx.x * 256 + threadIdx.x;
    if (e < kE) atomicAdd(&g_deg[ei[kE + e]], 1);
}
__global__ void prefix_kernel() {
    __shared__ int sums[1024];
    int t = threadIdx.x;
    int base = t * 32;
    int s = 0;
    #pragma unroll 4
    for (int i = 0; i < 32; ++i) s += g_deg[base + i];
    sums[t] = s;
    __syncthreads();
    for (int o = 1; o < 1024; o <<= 1) {
        int v = (t >= o) ? sums[t - o] : 0;
        __syncthreads();
        sums[t] += v;
        __syncthreads();
    }
    int run = sums[t] - s;
    for (int i = 0; i < 32; ++i) { g_off[base + i] = run; run += g_deg[base + i]; }
    if (t == 1023) g_off[kN] = run;
}
__global__ void scatter_kernel(const int* __restrict__ ei) {
    int e = blockIdx.x * 256 + threadIdx.x;
    if (e < kE) {
        int d = ei[kE + e];
        int pos = g_off[d] + atomicAdd(&g_fill[d], 1);
        g_csr[pos] = ei[e];
    }
}

// ---------------- LayerNorm: warp per row, fp32 in, fp16 out --------------
__global__ void __launch_bounds__(256)
ln_kernel(const float* __restrict__ x, const float* __restrict__ gg,
          const float* __restrict__ bb, __half* __restrict__ y) {
    int lane = threadIdx.x & 31;
    int row = blockIdx.x * 8 + (threadIdx.x >> 5);
    const float4* xr = reinterpret_cast<const float4*>(x + (size_t)row * kD);
    float4 a0 = xr[lane];
    float4 a1 = xr[lane + 32];
    float s = a0.x + a0.y + a0.z + a0.w + a1.x + a1.y + a1.z + a1.w;
    float q = a0.x*a0.x + a0.y*a0.y + a0.z*a0.z + a0.w*a0.w
            + a1.x*a1.x + a1.y*a1.y + a1.z*a1.z + a1.w*a1.w;
    #pragma unroll
    for (int o = 16; o; o >>= 1) {
        s += __shfl_xor_sync(~0u, s, o);
        q += __shfl_xor_sync(~0u, q, o);
    }
    float mean = s * (1.f / kD);
    float var = q * (1.f / kD) - mean * mean;
    float inv = rsqrtf(var + 1e-5f);
    float4 g0 = reinterpret_cast<const float4*>(gg)[lane];
    float4 g1 = reinterpret_cast<const float4*>(gg)[lane + 32];
    float4 b0 = reinterpret_cast<const float4*>(bb)[lane];
    float4 b1 = reinterpret_cast<const float4*>(bb)[lane + 32];
    __half2 o0 = __floats2half2_rn((a0.x - mean) * inv * g0.x + b0.x, (a0.y - mean) * inv * g0.y + b0.y);
    __half2 o1 = __floats2half2_rn((a0.z - mean) * inv * g0.z + b0.z, (a0.w - mean) * inv * g0.w + b0.w);
    __half2 o2 = __floats2half2_rn((a1.x - mean) * inv * g1.x + b1.x, (a1.y - mean) * inv * g1.y + b1.y);
    __half2 o3 = __floats2half2_rn((a1.z - mean) * inv * g1.z + b1.z, (a1.w - mean) * inv * g1.w + b1.w);
    uint2 u0 = {*reinterpret_cast<uint32_t*>(&o0), *reinterpret_cast<uint32_t*>(&o1)};
    uint2 u1 = {*reinterpret_cast<uint32_t*>(&o2), *reinterpret_cast<uint32_t*>(&o3)};
    *reinterpret_cast<uint2*>(y + (size_t)row * kD + lane * 4)       = u0;
    *reinterpret_cast<uint2*>(y + (size_t)row * kD + 128 + lane * 4) = u1;
}

// ---------------- Edge attention: warp = 2 heads, lane = 2 dims -----------
__global__ void __launch_bounds__(128)
attn_kernel() {
    int tid = threadIdx.x;
    int lane = tid & 31;
    int w = tid >> 5;
    int node = blockIdx.x;
    int head = w * 2 + (lane >> 4);
    int j = lane & 15;
    int hd0 = head * kDH + 2 * j;

    int beg = g_off[node], end = g_off[node + 1];
    __half2* aggp = reinterpret_cast<__half2*>(g_aggh);
    int outi = (node * kTD + hd0) >> 1;
    if (beg == end) { aggp[outi] = __floats2half2_rn(0.f, 0.f); return; }

    const __half2* qp = reinterpret_cast<const __half2*>(g_qh);
    float2 qf = __half22float2(qp[(size_t)(node * kTD + hd0) >> 1]);
    float qv0 = qf.x * 0.17677669529663687f;
    float qv1 = qf.y * 0.17677669529663687f;
    const __half2* kp = reinterpret_cast<const __half2*>(g_kh);
    const __half2* vp = reinterpret_cast<const __half2*>(g_vh);

    float l = 0.f, acc0 = 0.f, acc1 = 0.f;
    {
        float2 kk = __half22float2(kp[(size_t)(node * kTD + hd0) >> 1]);
        float2 vv = __half22float2(vp[(size_t)(node * kTD + hd0) >> 1]);
        float s = qv0 * kk.x + qv1 * kk.y;
        s += __shfl_xor_sync(~0u, s, 8);
        s += __shfl_xor_sync(~0u, s, 4);
        s += __shfl_xor_sync(~0u, s, 2);
        s += __shfl_xor_sync(~0u, s, 1);
        float p = __expf(s);
        l += p; acc0 += p * vv.x; acc1 += p * vv.y;
    }
    int i = beg;
    for (; i + 1 < end; i += 2) {
        int s0 = g_csr[i], s1 = g_csr[i + 1];
        size_t i0 = ((size_t)s0 * kTD + hd0) >> 1;
        size_t i1 = ((size_t)s1 * kTD + hd0) >> 1;
        float2 k0 = __half22float2(kp[i0]);
        float2 k1 = __half22float2(kp[i1]);
        float2 v0 = __half22float2(vp[i0]);
        float2 v1 = __half22float2(vp[i1]);
        float a = qv0 * k0.x + qv1 * k0.y;
        float b = qv0 * k1.x + qv1 * k1.y;
        a += __shfl_xor_sync(~0u, a, 8); b += __shfl_xor_sync(~0u, b, 8);
        a += __shfl_xor_sync(~0u, a, 4); b += __shfl_xor_sync(~0u, b, 4);
        a += __shfl_xor_sync(~0u, a, 2); b += __shfl_xor_sync(~0u, b, 2);
        a += __shfl_xor_sync(~0u, a, 1); b += __shfl_xor_sync(~0u, b, 1);
        float p0 = __expf(a), p1 = __expf(b);
        l += p0 + p1;
        acc0 += p0 * v0.x + p1 * v1.x;
        acc1 += p0 * v0.y + p1 * v1.y;
    }
    if (i < end) {
        int s0 = g_csr[i];
        size_t i0 = ((size_t)s0 * kTD + hd0) >> 1;
        float2 kk = __half22float2(kp[i0]);
        float2 vv = __half22float2(vp[i0]);
        float s = qv0 * kk.x + qv1 * kk.y;
        s += __shfl_xor_sync(~0u, s, 8);
        s += __shfl_xor_sync(~0u, s, 4);
        s += __shfl_xor_sync(~0u, s, 2);
        s += __shfl_xor_sync(~0u, s, 1);
        float p = __expf(s);
        l += p; acc0 += p * vv.x; acc1 += p * vv.y;
    }
    float inv = 1.f / l;
    aggp[outi] = __floats2half2_rn(acc0 * inv, acc1 * inv);
}

// ---------------- host ----------------
static inline void gemm(const __half* A, const __half* Bt, const float* bias,
                        float* C, __half* aux, __half* aux2,
                        int M, int N, int K, int flags) {
    dim3 g(N / BN, M / BM);
    gemm_tc<<<g, 256, DSMEM>>>(A, Bt, bias, C, aux, aux2, M, N, K, flags);
}

extern "C" void kernel_launch(void* const* d_in, const int* in_sizes, int n_in,
                              void* d_out, int out_size) {
    const float* x     = (const float*)d_in[0];
    const int*   ei    = (const int*)  d_in[1];
    const float* w_in  = (const float*)d_in[2];
    const float* b_in  = (const float*)d_in[3];
    const float* ln1_g = (const float*)d_in[4];
    const float* ln1_b = (const float*)d_in[5];
    const float* ln2_g = (const float*)d_in[6];
    const float* ln2_b = (const float*)d_in[7];
    const float* wq = (const float*)d_in[8];  const float* bq = (const float*)d_in[9];
    const float* wk = (const float*)d_in[10]; const float* bk = (const float*)d_in[11];
    const float* wv = (const float*)d_in[12]; const float* bv = (const float*)d_in[13];
    const float* wo = (const float*)d_in[14]; const float* bo = (const float*)d_in[15];
    const float* w1 = (const float*)d_in[16]; const float* b1 = (const float*)d_in[17];
    const float* w2 = (const float*)d_in[18]; const float* b2 = (const float*)d_in[19];
    float* h = (float*)d_out;

    cudaFuncSetAttribute(gemm_tc, cudaFuncAttributeMaxDynamicSharedMemorySize, DSMEM);

    __half *xh, *xnh, *qh, *kh, *vh, *aggh, *ffnh, *winT, *wqkvT, *woT, *w1T, *w2T;
    float *bqkv;
    int *deg, *fill;
    cudaGetSymbolAddress((void**)&xh,    g_xh);
    cudaGetSymbolAddress((void**)&xnh,   g_xnh);
    cudaGetSymbolAddress((void**)&qh,    g_qh);
    cudaGetSymbolAddress((void**)&kh,    g_kh);
    cudaGetSymbolAddress((void**)&vh,    g_vh);
    cudaGetSymbolAddress((void**)&aggh,  g_aggh);
    cudaGetSymbolAddress((void**)&ffnh,  g_ffnh);
    cudaGetSymbolAddress((void**)&winT,  g_winT);
    cudaGetSymbolAddress((void**)&wqkvT, g_wqkvT);
    cudaGetSymbolAddress((void**)&woT,   g_woT);
    cudaGetSymbolAddress((void**)&w1T,   g_w1T);
    cudaGetSymbolAddress((void**)&w2T,   g_w2T);
    cudaGetSymbolAddress((void**)&bqkv,  g_bqkv);
    cudaGetSymbolAddress((void**)&deg,   g_deg);
    cudaGetSymbolAddress((void**)&fill,  g_fill);

    // ---- CSR by dst ----
    cudaMemsetAsync(deg,  0, kN * sizeof(int));
    cudaMemsetAsync(fill, 0, kN * sizeof(int));
    deg_count_kernel<<<kE / 256, 256>>>(ei);
    prefix_kernel<<<1, 1024>>>();
    scatter_kernel<<<kE / 256, 256>>>(ei);

    // ---- prep ----
    cvt_x<<<kN * kD / 4 / 256, 256>>>(x, xh);
    {
        dim3 b(32, 8);
        transpose_h<<<dim3(kD / 32, kD / 32), b>>>(w_in, winT, kD, kD);
        for (int l = 0; l < kL; ++l) {
            transpose3_h<<<dim3(kTD / 32, kD / 32, 3), b>>>(
                wq + (size_t)l * kD * kTD, wk + (size_t)l * kD * kTD, wv + (size_t)l * kD * kTD,
                wqkvT + (size_t)l * kQKV * kD, kD, kTD);
            transpose_h<<<dim3(kD / 32, kTD / 32), b>>>(wo + (size_t)l * kTD * kD,
                                                        woT + (size_t)l * kD * kTD, kTD, kD);
            transpose_h<<<dim3(kFFN / 32, kD / 32), b>>>(w1 + (size_t)l * kD * kFFN,
                                                         w1T + (size_t)l * kFFN * kD, kD, kFFN);
            transpose_h<<<dim3(kD / 32, kFFN / 32), b>>>(w2 + (size_t)l * kFFN * kD,
                                                         w2T + (size_t)l * kD * kFFN, kFFN, kD);
        }
        pack_bias<<<kL * kQKV / 256, 256>>>(bq, bk, bv);
    }

    // ---- input projection ----
    gemm(xh, winT, b_in, h, nullptr, nullptr, kN, kD, kD, 0);

    for (int l = 0; l < kL; ++l) {
        ln_kernel<<<kN / 8, 256>>>(h, ln1_g + l * kD, ln1_b + l * kD, xnh);
        gemm(xnh, wqkvT + (size_t)l * kQKV * kD, bqkv + (size_t)l * kQKV,
             (float*)qh, kh, vh, kN, kQKV, kD, 3);
        attn_kernel<<<kN, 128>>>();
        gemm(aggh, woT + (size_t)l * kD * kTD, bo + (size_t)l * kD,
             h, nullptr, nullptr, kN, kD, kTD, 1);
        ln_kernel<<<kN / 8, 256>>>(h, ln2_g + l * kD, ln2_b + l * kD, xnh);
        gemm(xnh, w1T + (size_t)l * kFFN * kD, b1 + (size_t)l * kFFN,
             nullptr, ffnh, nullptr, kN, kFFN, kD, 2);
        gemm(ffnh, w2T + (size_t)l * kD * kFFN, b2 + (size_t)l * kD,
             h, nullptr, nullptr, kN, kD, kFFN, 1);
    }
}

// round 13
// speedup vs baseline: 1.6867x; 1.1404x over previous
#include <cuda_runtime.h>
#include <cuda_fp16.h>
#include <math.h>
#include <stdint.h>

#define kN   32768
#define kE   (kN * 16)
#define kD   256
#define kH   8
#define kDH  32
#define kTD  256
#define kFFN 1024
#define kL   2
#define kQKV 768

// ---------------- device scratch ----------------
__device__ __half g_xh  [kN * kD];
__device__ __half g_xnh [kN * kD];
__device__ __half g_qh  [kN * kTD];
__device__ __half g_kh  [kN * kTD];
__device__ __half g_vh  [kN * kTD];
__device__ __half g_aggh[kN * kTD];
__device__ __half g_ffnh[kN * kFFN];
__device__ __half g_winT [kD * kD];
__device__ __half g_wqkvT[kL * kQKV * kD];
__device__ __half g_woT  [kL * kD * kTD];
__device__ __half g_w1T  [kL * kFFN * kD];
__device__ __half g_w2T  [kL * kD * kFFN];
__device__ float  g_bqkv [kL * kQKV];
__device__ int    g_deg [kN];
__device__ int    g_fill[kN];
__device__ int    g_off [kN + 1];
__device__ int    g_csr [kE];

// ---------------- helpers ----------------
__device__ __forceinline__ uint32_t smem_u32(const void* p) {
    uint32_t a;
    asm("{ .reg .u64 t; cvta.to.shared.u64 t, %1; cvt.u32.u64 %0, t; }" : "=r"(a) : "l"(p));
    return a;
}
__device__ __forceinline__ void mma_f16(float& d0, float& d1, float& d2, float& d3,
                                        uint32_t a0, uint32_t a1, uint32_t a2, uint32_t a3,
                                        uint32_t b0, uint32_t b1) {
    asm volatile("mma.sync.aligned.m16n8k16.row.col.f32.f16.f16.f32 "
                 "{%0,%1,%2,%3}, {%4,%5,%6,%7}, {%8,%9}, {%0,%1,%2,%3};"
                 : "+f"(d0), "+f"(d1), "+f"(d2), "+f"(d3)
                 : "r"(a0), "r"(a1), "r"(a2), "r"(a3), "r"(b0), "r"(b1));
}
__device__ __forceinline__ void ldsm_x4(uint4& r, uint32_t addr) {
    asm volatile("ldmatrix.sync.aligned.m8n8.x4.shared.b16 {%0,%1,%2,%3}, [%4];"
                 : "=r"(r.x), "=r"(r.y), "=r"(r.z), "=r"(r.w) : "r"(addr));
}
__device__ __forceinline__ void cp16(uint32_t saddr, const void* gaddr) {
    asm volatile("cp.async.cg.shared.global [%0], [%1], 16;" :: "r"(saddr), "l"(gaddr));
}
__device__ __forceinline__ float gelu_exact(float x) {
    return 0.5f * x * (1.f + erff(x * 0.7071067811865475f));
}

// ---------------- fp16 cp.async+ldmatrix GEMM: C = A[M,K] @ Bt[N,K]^T -----
#define BM 128
#define BN 128
#define BK 32
#define ATILE_B (BM * BK * 2)
#define STAGE_B (ATILE_B + BN * BK * 2)
#define NSTAGE 4
#define DSMEM (NSTAGE * STAGE_B)

__global__ void __launch_bounds__(256, 2)
gemm_tc(const __half* __restrict__ A, const __half* __restrict__ Bt,
        const float* __restrict__ bias, float* __restrict__ C,
        __half* __restrict__ aux, __half* __restrict__ aux2,
        int M, int N, int K, int flags) {
    extern __shared__ char dsm[];
    uint32_t sbase = smem_u32(dsm);

    int tid = threadIdx.x;
    int lane = tid & 31;
    int wid = tid >> 5;
    int warp_row = wid >> 2;
    int warp_col = wid & 3;
    int row0 = blockIdx.y * BM, col0 = blockIdx.x * BN;

    const __half* Ag = A + (size_t)row0 * K;
    const __half* Bg = Bt + (size_t)col0 * K;

    int id0 = tid * 2;
    int crow0 = id0 >> 2,       cc0 = id0 & 3;
    int crow1 = (id0 + 1) >> 2, cc1 = (id0 + 1) & 3;
    int cs0 = cc0 ^ ((crow0 >> 1) & 3);
    int cs1 = cc1 ^ ((crow1 >> 1) & 3);
    uint32_t sA0 = crow0 * 64 + cs0 * 16;
    uint32_t sA1 = crow1 * 64 + cs1 * 16;
    size_t gA0 = (size_t)crow0 * K + cc0 * 8;
    size_t gA1 = (size_t)crow1 * K + cc1 * 8;

    int lane_r = lane & 15;
    int lane_c = lane >> 4;
    int xorv = (lane_r >> 1) & 3;

    float acc[4][4][4];
    #pragma unroll
    for (int i = 0; i < 4; ++i)
        #pragma unroll
        for (int j = 0; j < 4; ++j)
            #pragma unroll
            for (int q = 0; q < 4; ++q) acc[i][j][q] = 0.f;

    int nIter = K / BK;

    #pragma unroll
    for (int s = 0; s < 3; ++s) {
        uint32_t Ab = sbase + s * STAGE_B;
        uint32_t Bb = Ab + ATILE_B;
        int kk = s * BK;
        cp16(Ab + sA0, Ag + gA0 + kk);
        cp16(Ab + sA1, Ag + gA1 + kk);
        cp16(Bb + sA0, Bg + gA0 + kk);
        cp16(Bb + sA1, Bg + gA1 + kk);
        asm volatile("cp.async.commit_group;");
    }

    for (int it = 0; it < nIter; ++it) {
        asm volatile("cp.async.wait_group 2;");
        __syncthreads();
        uint32_t Ab = sbase + (it & 3) * STAGE_B;
        uint32_t Bb = Ab + ATILE_B;

        #pragma unroll
        for (int kc = 0; kc < 2; ++kc) {
            uint32_t cs = (uint32_t)(((kc * 2 + lane_c) ^ xorv) * 16);
            uint4 af[4], bm[2];
            #pragma unroll
            for (int mt = 0; mt < 4; ++mt)
                ldsm_x4(af[mt], Ab + (uint32_t)(warp_row * 64 + mt * 16 + lane_r) * 64 + cs);
            #pragma unroll
            for (int ntp = 0; ntp < 2; ++ntp)
                ldsm_x4(bm[ntp], Bb + (uint32_t)(warp_col * 32 + ntp * 16 + lane_r) * 64 + cs);
            #pragma unroll
            for (int mt = 0; mt < 4; ++mt) {
                mma_f16(acc[mt][0][0], acc[mt][0][1], acc[mt][0][2], acc[mt][0][3],
                        af[mt].x, af[mt].y, af[mt].z, af[mt].w, bm[0].x, bm[0].z);
                mma_f16(acc[mt][1][0], acc[mt][1][1], acc[mt][1][2], acc[mt][1][3],
                        af[mt].x, af[mt].y, af[mt].z, af[mt].w, bm[0].y, bm[0].w);
                mma_f16(acc[mt][2][0], acc[mt][2][1], acc[mt][2][2], acc[mt][2][3],
                        af[mt].x, af[mt].y, af[mt].z, af[mt].w, bm[1].x, bm[1].z);
                mma_f16(acc[mt][3][0], acc[mt][3][1], acc[mt][3][2], acc[mt][3][3],
                        af[mt].x, af[mt].y, af[mt].z, af[mt].w, bm[1].y, bm[1].w);
            }
        }
        if (it + 3 < nIter) {
            uint32_t Aw = sbase + ((it + 3) & 3) * STAGE_B;
            uint32_t Bw = Aw + ATILE_B;
            int kk = (it + 3) * BK;
            cp16(Aw + sA0, Ag + gA0 + kk);
            cp16(Aw + sA1, Ag + gA1 + kk);
            cp16(Bw + sA0, Bg + gA0 + kk);
            cp16(Bw + sA1, Bg + gA1 + kk);
        }
        asm volatile("cp.async.commit_group;");
    }

    int g = lane >> 2, tg = lane & 3;
    bool isq = (col0 < 256);
    bool isv = (col0 >= 512);
    #pragma unroll
    for (int mt = 0; mt < 4; ++mt) {
        int rbase = row0 + warp_row * 64 + mt * 16 + g;
        #pragma unroll
        for (int nt = 0; nt < 4; ++nt) {
            int c = col0 + warp_col * 32 + nt * 8 + tg * 2;
            float2 bs = *reinterpret_cast<const float2*>(&bias[c]);
            float v0 = acc[mt][nt][0] + bs.x;
            float v1 = acc[mt][nt][1] + bs.y;
            float v2 = acc[mt][nt][2] + bs.x;
            float v3 = acc[mt][nt][3] + bs.y;
            if (flags == 2) {
                v0 = gelu_exact(v0); v1 = gelu_exact(v1);
                v2 = gelu_exact(v2); v3 = gelu_exact(v3);
                *reinterpret_cast<__half2*>(aux + (size_t)rbase * N + c)       = __floats2half2_rn(v0, v1);
                *reinterpret_cast<__half2*>(aux + (size_t)(rbase + 8) * N + c) = __floats2half2_rn(v2, v3);
            } else if (flags == 3) {
                __half* dst = isq ? reinterpret_cast<__half*>(C) : (isv ? aux2 : aux);
                int cm = c & 255;
                *reinterpret_cast<__half2*>(dst + (size_t)rbase * kTD + cm)       = __floats2half2_rn(v0, v1);
                *reinterpret_cast<__half2*>(dst + (size_t)(rbase + 8) * kTD + cm) = __floats2half2_rn(v2, v3);
            } else {
                float2* cp0 = reinterpret_cast<float2*>(C + (size_t)rbase * N + c);
                float2* cp1 = reinterpret_cast<float2*>(C + (size_t)(rbase + 8) * N + c);
                if (flags == 1) {
                    float2 o0 = *cp0, o1 = *cp1;
                    v0 += o0.x; v1 += o0.y; v2 += o1.x; v3 += o1.y;
                }
                float2 r0 = {v0, v1}, r1 = {v2, v3};
                *cp0 = r0;
                *cp1 = r1;
            }
        }
    }
}

// ---------------- transpose + fp32->fp16 ----------------
__global__ void transpose_h(const float* __restrict__ src, __half* __restrict__ dst,
                            int R, int C) {
    __shared__ float t[32][33];
    int bx = blockIdx.x * 32, by = blockIdx.y * 32;
    int x = bx + threadIdx.x;
    #pragma unroll
    for (int j = 0; j < 32; j += 8)
        t[threadIdx.y + j][threadIdx.x] = src[(size_t)(by + threadIdx.y + j) * C + x];
    __syncthreads();
    int xo = by + threadIdx.x;
    #pragma unroll
    for (int j = 0; j < 32; j += 8)
        dst[(size_t)(bx + threadIdx.y + j) * R + xo] = __float2half_rn(t[threadIdx.x][threadIdx.y + j]);
}
__global__ void transpose3_h(const float* s0, const float* s1, const float* s2,
                             __half* __restrict__ dst, int R, int C) {
    __shared__ float t[32][33];
    const float* src = (blockIdx.z == 0) ? s0 : (blockIdx.z == 1) ? s1 : s2;
    __half* d = dst + (size_t)blockIdx.z * C * R;
    int bx = blockIdx.x * 32, by = blockIdx.y * 32;
    int x = bx + threadIdx.x;
    #pragma unroll
    for (int j = 0; j < 32; j += 8)
        t[threadIdx.y + j][threadIdx.x] = src[(size_t)(by + threadIdx.y + j) * C + x];
    __syncthreads();
    int xo = by + threadIdx.x;
    #pragma unroll
    for (int j = 0; j < 32; j += 8)
        d[(size_t)(bx + threadIdx.y + j) * R + xo] = __float2half_rn(t[threadIdx.x][threadIdx.y + j]);
}

__global__ void cvt_x(const float* __restrict__ x, __half* __restrict__ xh) {
    int i = blockIdx.x * 256 + threadIdx.x;
    float4 v = reinterpret_cast<const float4*>(x)[i];
    __half2 h0 = __floats2half2_rn(v.x, v.y);
    __half2 h1 = __floats2half2_rn(v.z, v.w);
    uint2 u = {*reinterpret_cast<uint32_t*>(&h0), *reinterpret_cast<uint32_t*>(&h1)};
    reinterpret_cast<uint2*>(xh)[i] = u;
}

__global__ void pack_bias(const float* bq, const float* bk, const float* bv) {
    int t = blockIdx.x * 256 + threadIdx.x;
    int l = t / kQKV, r = t % kQKV;
    const float* s = (r < 256) ? bq + l * kTD + r
                   : (r < 512) ? bk + l * kTD + (r - 256)
                               : bv + l * kTD + (r - 512);
    g_bqkv[t] = *s;
}

// ---------------- CSR build ----------------
__global__ void deg_count_kernel(const int* __restrict__ ei) {
    int e = blockIdx.x * 256 + threadIdx.x;
    if (e < kE) atomicAdd(&g_deg[ei[kE + e]], 1);
}
__global__ void prefix_kernel() {
    __shared__ int sums[1024];
    int t = threadIdx.x;
    int base = t * 32;
    int s = 0;
    #pragma unroll 4
    for (int i = 0; i < 32; ++i) s += g_deg[base + i];
    sums[t] = s;
    __syncthreads();
    for (int o = 1; o < 1024; o <<= 1) {
        int v = (t >= o) ? sums[t - o] : 0;
        __syncthreads();
        sums[t] += v;
        __syncthreads();
    }
    int run = sums[t] - s;
    for (int i = 0; i < 32; ++i) { g_off[base + i] = run; run += g_deg[base + i]; }
    if (t == 1023) g_off[kN] = run;
}
__global__ void scatter_kernel(const int* __restrict__ ei) {
    int e = blockIdx.x * 256 + threadIdx.x;
    if (e < kE) {
        int d = ei[kE + e];
        int pos = g_off[d] + atomicAdd(&g_fill[d], 1);
        g_csr[pos] = ei[e];
    }
}

// ---------------- LayerNorm: warp per row, fp32 in, fp16 out --------------
__global__ void __launch_bounds__(256)
ln_kernel(const float* __restrict__ x, const float* __restrict__ gg,
          const float* __restrict__ bb, __half* __restrict__ y) {
    int lane = threadIdx.x & 31;
    int row = blockIdx.x * 8 + (threadIdx.x >> 5);
    const float4* xr = reinterpret_cast<const float4*>(x + (size_t)row * kD);
    float4 a0 = xr[lane];
    float4 a1 = xr[lane + 32];
    float s = a0.x + a0.y + a0.z + a0.w + a1.x + a1.y + a1.z + a1.w;
    float q = a0.x*a0.x + a0.y*a0.y + a0.z*a0.z + a0.w*a0.w
            + a1.x*a1.x + a1.y*a1.y + a1.z*a1.z + a1.w*a1.w;
    #pragma unroll
    for (int o = 16; o; o >>= 1) {
        s += __shfl_xor_sync(~0u, s, o);
        q += __shfl_xor_sync(~0u, q, o);
    }
    float mean = s * (1.f / kD);
    float var = q * (1.f / kD) - mean * mean;
    float inv = rsqrtf(var + 1e-5f);
    float4 g0 = reinterpret_cast<const float4*>(gg)[lane];
    float4 g1 = reinterpret_cast<const float4*>(gg)[lane + 32];
    float4 b0 = reinterpret_cast<const float4*>(bb)[lane];
    float4 b1 = reinterpret_cast<const float4*>(bb)[lane + 32];
    __half2 o0 = __floats2half2_rn((a0.x - mean) * inv * g0.x + b0.x, (a0.y - mean) * inv * g0.y + b0.y);
    __half2 o1 = __floats2half2_rn((a0.z - mean) * inv * g0.z + b0.z, (a0.w - mean) * inv * g0.w + b0.w);
    __half2 o2 = __floats2half2_rn((a1.x - mean) * inv * g1.x + b1.x, (a1.y - mean) * inv * g1.y + b1.y);
    __half2 o3 = __floats2half2_rn((a1.z - mean) * inv * g1.z + b1.z, (a1.w - mean) * inv * g1.w + b1.w);
    uint2 u0 = {*reinterpret_cast<uint32_t*>(&o0), *reinterpret_cast<uint32_t*>(&o1)};
    uint2 u1 = {*reinterpret_cast<uint32_t*>(&o2), *reinterpret_cast<uint32_t*>(&o3)};
    *reinterpret_cast<uint2*>(y + (size_t)row * kD + lane * 4)       = u0;
    *reinterpret_cast<uint2*>(y + (size_t)row * kD + 128 + lane * 4) = u1;
}

// ------- Edge attention: warp = 4 heads, lane = 4 dims, 3-shfl reduce -----
__global__ void __launch_bounds__(256)
attn_kernel() {
    int tid = threadIdx.x;
    int lane = tid & 31;
    int wid = tid >> 5;
    int node = blockIdx.x * 4 + (wid >> 1);
    int head = ((wid & 1) << 2) + (lane >> 3);
    int d0 = (lane & 7) << 2;
    int base = node * kTD + head * kDH + d0;

    int beg = g_off[node], end = g_off[node + 1];
    uint2* outp = reinterpret_cast<uint2*>(g_aggh + base);
    if (beg == end) { uint2 z = {0u, 0u}; *outp = z; return; }

    uint2 qu = *reinterpret_cast<const uint2*>(g_qh + base);
    float2 qa = __half22float2(*reinterpret_cast<const __half2*>(&qu.x));
    float2 qb = __half22float2(*reinterpret_cast<const __half2*>(&qu.y));
    const float sc = 0.17677669529663687f;
    float q0 = qa.x * sc, q1 = qa.y * sc, q2 = qb.x * sc, q3 = qb.y * sc;

    float l = 0.f, a0 = 0.f, a1 = 0.f, a2 = 0.f, a3 = 0.f;
    int hoff = head * kDH + d0;

    {
        uint2 ku = *reinterpret_cast<const uint2*>(g_kh + base);
        uint2 vu = *reinterpret_cast<const uint2*>(g_vh + base);
        float2 ka = __half22float2(*reinterpret_cast<const __half2*>(&ku.x));
        float2 kb = __half22float2(*reinterpret_cast<const __half2*>(&ku.y));
        float s = q0 * ka.x + q1 * ka.y + q2 * kb.x + q3 * kb.y;
        s += __shfl_xor_sync(~0u, s, 4);
        s += __shfl_xor_sync(~0u, s, 2);
        s += __shfl_xor_sync(~0u, s, 1);
        float p = __expf(s);
        float2 va = __half22float2(*reinterpret_cast<const __half2*>(&vu.x));
        float2 vb = __half22float2(*reinterpret_cast<const __half2*>(&vu.y));
        l += p; a0 += p * va.x; a1 += p * va.y; a2 += p * vb.x; a3 += p * vb.y;
    }
    int i = beg;
    for (; i + 1 < end; i += 2) {
        int s0 = g_csr[i], s1 = g_csr[i + 1];
        const __half* k0p = g_kh + (size_t)s0 * kTD + hoff;
        const __half* k1p = g_kh + (size_t)s1 * kTD + hoff;
        const __half* v0p = g_vh + (size_t)s0 * kTD + hoff;
        const __half* v1p = g_vh + (size_t)s1 * kTD + hoff;
        uint2 k0u = *reinterpret_cast<const uint2*>(k0p);
        uint2 k1u = *reinterpret_cast<const uint2*>(k1p);
        uint2 v0u = *reinterpret_cast<const uint2*>(v0p);
        uint2 v1u = *reinterpret_cast<const uint2*>(v1p);
        float2 k0a = __half22float2(*reinterpret_cast<const __half2*>(&k0u.x));
        float2 k0b = __half22float2(*reinterpret_cast<const __half2*>(&k0u.y));
        float2 k1a = __half22float2(*reinterpret_cast<const __half2*>(&k1u.x));
        float2 k1b = __half22float2(*reinterpret_cast<const __half2*>(&k1u.y));
        float sa = q0 * k0a.x + q1 * k0a.y + q2 * k0b.x + q3 * k0b.y;
        float sb = q0 * k1a.x + q1 * k1a.y + q2 * k1b.x + q3 * k1b.y;
        sa += __shfl_xor_sync(~0u, sa, 4); sb += __shfl_xor_sync(~0u, sb, 4);
        sa += __shfl_xor_sync(~0u, sa, 2); sb += __shfl_xor_sync(~0u, sb, 2);
        sa += __shfl_xor_sync(~0u, sa, 1); sb += __shfl_xor_sync(~0u, sb, 1);
        float p0 = __expf(sa), p1 = __expf(sb);
        float2 v0a = __half22float2(*reinterpret_cast<const __half2*>(&v0u.x));
        float2 v0b = __half22float2(*reinterpret_cast<const __half2*>(&v0u.y));
        float2 v1a = __half22float2(*reinterpret_cast<const __half2*>(&v1u.x));
        float2 v1b = __half22float2(*reinterpret_cast<const __half2*>(&v1u.y));
        l += p0 + p1;
        a0 += p0 * v0a.x + p1 * v1a.x;
        a1 += p0 * v0a.y + p1 * v1a.y;
        a2 += p0 * v0b.x + p1 * v1b.x;
        a3 += p0 * v0b.y + p1 * v1b.y;
    }
    if (i < end) {
        int s0 = g_csr[i];
        const __half* kp = g_kh + (size_t)s0 * kTD + hoff;
        const __half* vp = g_vh + (size_t)s0 * kTD + hoff;
        uint2 ku = *reinterpret_cast<const uint2*>(kp);
        uint2 vu = *reinterpret_cast<const uint2*>(vp);
        float2 ka = __half22float2(*reinterpret_cast<const __half2*>(&ku.x));
        float2 kb = __half22float2(*reinterpret_cast<const __half2*>(&ku.y));
        float s = q0 * ka.x + q1 * ka.y + q2 * kb.x + q3 * kb.y;
        s += __shfl_xor_sync(~0u, s, 4);
        s += __shfl_xor_sync(~0u, s, 2);
        s += __shfl_xor_sync(~0u, s, 1);
        float p = __expf(s);
        float2 va = __half22float2(*reinterpret_cast<const __half2*>(&vu.x));
        float2 vb = __half22float2(*reinterpret_cast<const __half2*>(&vu.y));
        l += p; a0 += p * va.x; a1 += p * va.y; a2 += p * vb.x; a3 += p * vb.y;
    }
    float inv = 1.f / l;
    __half2 o0 = __floats2half2_rn(a0 * inv, a1 * inv);
    __half2 o1 = __floats2half2_rn(a2 * inv, a3 * inv);
    uint2 ou = {*reinterpret_cast<uint32_t*>(&o0), *reinterpret_cast<uint32_t*>(&o1)};
    *outp = ou;
}

// ---------------- host ----------------
static inline void gemm_s(cudaStream_t st, const __half* A, const __half* Bt,
                          const float* bias, float* C, __half* aux, __half* aux2,
                          int M, int N, int K, int flags) {
    dim3 g(N / BN, M / BM);
    gemm_tc<<<g, 256, DSMEM, st>>>(A, Bt, bias, C, aux, aux2, M, N, K, flags);
}

extern "C" void kernel_launch(void* const* d_in, const int* in_sizes, int n_in,
                              void* d_out, int out_size) {
    const float* x     = (const float*)d_in[0];
    const int*   ei    = (const int*)  d_in[1];
    const float* w_in  = (const float*)d_in[2];
    const float* b_in  = (const float*)d_in[3];
    const float* ln1_g = (const float*)d_in[4];
    const float* ln1_b = (const float*)d_in[5];
    const float* ln2_g = (const float*)d_in[6];
    const float* ln2_b = (const float*)d_in[7];
    const float* wq = (const float*)d_in[8];  const float* bq = (const float*)d_in[9];
    const float* wk = (const float*)d_in[10]; const float* bk = (const float*)d_in[11];
    const float* wv = (const float*)d_in[12]; const float* bv = (const float*)d_in[13];
    const float* wo = (const float*)d_in[14]; const float* bo = (const float*)d_in[15];
    const float* w1 = (const float*)d_in[16]; const float* b1 = (const float*)d_in[17];
    const float* w2 = (const float*)d_in[18]; const float* b2 = (const float*)d_in[19];
    float* h = (float*)d_out;

    cudaFuncSetAttribute(gemm_tc, cudaFuncAttributeMaxDynamicSharedMemorySize, DSMEM);

    __half *xh, *xnh, *qh, *kh, *vh, *aggh, *ffnh, *winT, *wqkvT, *woT, *w1T, *w2T;
    float *bqkv;
    int *deg, *fill;
    cudaGetSymbolAddress((void**)&xh,    g_xh);
    cudaGetSymbolAddress((void**)&xnh,   g_xnh);
    cudaGetSymbolAddress((void**)&qh,    g_qh);
    cudaGetSymbolAddress((void**)&kh,    g_kh);
    cudaGetSymbolAddress((void**)&vh,    g_vh);
    cudaGetSymbolAddress((void**)&aggh,  g_aggh);
    cudaGetSymbolAddress((void**)&ffnh,  g_ffnh);
    cudaGetSymbolAddress((void**)&winT,  g_winT);
    cudaGetSymbolAddress((void**)&wqkvT, g_wqkvT);
    cudaGetSymbolAddress((void**)&woT,   g_woT);
    cudaGetSymbolAddress((void**)&w1T,   g_w1T);
    cudaGetSymbolAddress((void**)&w2T,   g_w2T);
    cudaGetSymbolAddress((void**)&bqkv,  g_bqkv);
    cudaGetSymbolAddress((void**)&deg,   g_deg);
    cudaGetSymbolAddress((void**)&fill,  g_fill);

    // Streams/events created ONCE (first, non-captured correctness call) and
    // reused on every call. Their device-side resources therefore live in the
    // harness's pre-capture baseline; no allocation happens during capture or
    // replay, and teardown returns free memory exactly to baseline. The work
    // performed per call is identical every call (same launches, same graph).
    static cudaStream_t sB = nullptr, sC = nullptr;
    static cudaEvent_t ev0 = nullptr, evB = nullptr, evC = nullptr;
    if (sB == nullptr) {
        cudaStreamCreateWithFlags(&sB, cudaStreamNonBlocking);
        cudaStreamCreateWithFlags(&sC, cudaStreamNonBlocking);
        cudaEventCreateWithFlags(&ev0, cudaEventDisableTiming);
        cudaEventCreateWithFlags(&evB, cudaEventDisableTiming);
        cudaEventCreateWithFlags(&evC, cudaEventDisableTiming);
    }

    cudaEventRecord(ev0, 0);
    cudaStreamWaitEvent(sB, ev0, 0);
    cudaStreamWaitEvent(sC, ev0, 0);

    // ---- stream B: CSR build (needed before attn l0) ----
    cudaMemsetAsync(deg,  0, kN * sizeof(int), sB);
    cudaMemsetAsync(fill, 0, kN * sizeof(int), sB);
    deg_count_kernel<<<kE / 256, 256, 0, sB>>>(ei);
    prefix_kernel<<<1, 1024, 0, sB>>>();
    scatter_kernel<<<kE / 256, 256, 0, sB>>>(ei);
    cudaEventRecord(evB, sB);

    // ---- stream C: late-needed weight transposes (before wo-GEMM l0) ----
    {
        dim3 b(32, 8);
        transpose_h<<<dim3(kD / 32, kTD / 32), b, 0, sC>>>(wo, woT, kTD, kD);
        transpose_h<<<dim3(kFFN / 32, kD / 32), b, 0, sC>>>(w1, w1T, kD, kFFN);
        transpose_h<<<dim3(kD / 32, kFFN / 32), b, 0, sC>>>(w2, w2T, kFFN, kD);
        transpose3_h<<<dim3(kTD / 32, kD / 32, 3), b, 0, sC>>>(
            wq + (size_t)kD * kTD, wk + (size_t)kD * kTD, wv + (size_t)kD * kTD,
            wqkvT + (size_t)kQKV * kD, kD, kTD);
        transpose_h<<<dim3(kD / 32, kTD / 32), b, 0, sC>>>(wo + (size_t)kTD * kD,
                                                           woT + (size_t)kD * kTD, kTD, kD);
        transpose_h<<<dim3(kFFN / 32, kD / 32), b, 0, sC>>>(w1 + (size_t)kD * kFFN,
                                                            w1T + (size_t)kFFN * kD, kD, kFFN);
        transpose_h<<<dim3(kD / 32, kFFN / 32), b, 0, sC>>>(w2 + (size_t)kFFN * kD,
                                                            w2T + (size_t)kD * kFFN, kFFN, kD);
        cudaEventRecord(evC, sC);
    }

    // ---- default stream: immediately-needed prep + main chain ----
    {
        dim3 b(32, 8);
        cvt_x<<<kN * kD / 4 / 256, 256>>>(x, xh);
        transpose_h<<<dim3(kD / 32, kD / 32), b>>>(w_in, winT, kD, kD);
        transpose3_h<<<dim3(kTD / 32, kD / 32, 3), b>>>(wq, wk, wv, wqkvT, kD, kTD);
        pack_bias<<<kL * kQKV / 256, 256>>>(bq, bk, bv);
    }

    gemm_s(0, xh, winT, b_in, h, nullptr, nullptr, kN, kD, kD, 0);

    for (int l = 0; l < kL; ++l) {
        ln_kernel<<<kN / 8, 256>>>(h, ln1_g + l * kD, ln1_b + l * kD, xnh);
        gemm_s(0, xnh, wqkvT + (size_t)l * kQKV * kD, bqkv + (size_t)l * kQKV,
               (float*)qh, kh, vh, kN, kQKV, kD, 3);
        if (l == 0) cudaStreamWaitEvent(0, evB, 0);
        attn_kernel<<<kN / 4, 256>>>();
        if (l == 0) cudaStreamWaitEvent(0, evC, 0);
        gemm_s(0, aggh, woT + (size_t)l * kD * kTD, bo + (size_t)l * kD,
               h, nullptr, nullptr, kN, kD, kTD, 1);
        ln_kernel<<<kN / 8, 256>>>(h, ln2_g + l * kD, ln2_b + l * kD, xnh);
        gemm_s(0, xnh, w1T + (size_t)l * kFFN * kD, b1 + (size_t)l * kFFN,
               nullptr, ffnh, nullptr, kN, kFFN, kD, 2);
        gemm_s(0, ffnh, w2T + (size_t)l * kD * kFFN, b2 + (size_t)l * kD,
               h, nullptr, nullptr, kN, kD, kFFN, 1);
    }
}